// round 8
// baseline (speedup 1.0000x reference)
#include <cuda_runtime.h>
#include <math.h>

// Problem constants
#define BATCH 4
#define SEQ   2048
#define HID   1024
#define MTOT  (BATCH * SEQ)   // 8192

// SGEMM tile config
#define BM 128
#define BN 128
#define BK 16
#define TM 8
#define TN 8
// threads = (BM/TM)*(BN/TN) = 256
// Fragment mapping: thread (tx,ty) owns rows {ty*4+i, 64+ty*4+i} (i=0..3)
// and cols {tx*4+j, 64+tx*4+j} (j=0..3): conflict-free LDS.128 (16B lane stride).

// Scratch (device globals are the sanctioned scratch mechanism)
__device__ float g_Q[(size_t)MTOT * HID];
__device__ float g_K[(size_t)MTOT * HID];
__device__ float g_V[(size_t)MTOT * HID];
__device__ float g_P[(size_t)BATCH * SEQ * SEQ];

// ---------------------------------------------------------------------------
// Fused QKV NT GEMM: for z = blockIdx.z in {0,1,2}:
//   {Q,K,V}[m,n] = sum_k X[m,k] * W{q,k,v}[n,k] + b{q,k,v}[n]
// Register prefetch + double-buffered smem; one __syncthreads per K-iter.
// ---------------------------------------------------------------------------
__global__ __launch_bounds__(256, 2) void gemm_qkv(
    const float* __restrict__ X,
    const float* __restrict__ Wq, const float* __restrict__ bq,
    const float* __restrict__ Wk, const float* __restrict__ bk,
    const float* __restrict__ Wv, const float* __restrict__ bv,
    float* __restrict__ Qo, float* __restrict__ Ko, float* __restrict__ Vo)
{
    const int z = blockIdx.z;
    const float* B    = (z == 0) ? Wq : (z == 1) ? Wk : Wv;
    const float* bias = (z == 0) ? bq : (z == 1) ? bk : bv;
    float*       C    = (z == 0) ? Qo : (z == 1) ? Ko : Vo;
    const int K = HID, N = HID;

    __shared__ float As[2][BK][BM];
    __shared__ float Bs[2][BK][BN];

    const int tid = threadIdx.x;
    const int tx  = tid % 16;
    const int ty  = tid / 16;
    const int row0 = blockIdx.y * BM;
    const int col0 = blockIdx.x * BN;

    const int la_r = tid >> 2;        // 0..63
    const int la_c = (tid & 3) * 4;   // 0,4,8,12

    const float* Ap = X + (long)(row0 + la_r) * K + la_c;
    const float* Bp = B + (long)(col0 + la_r) * K + la_c;

    float acc[TM][TN];
    #pragma unroll
    for (int i = 0; i < TM; i++)
        #pragma unroll
        for (int j = 0; j < TN; j++) acc[i][j] = 0.f;

    {
        float4 a0 = *(const float4*)(Ap);
        float4 a1 = *(const float4*)(Ap + 64 * K);
        float4 b0 = *(const float4*)(Bp);
        float4 b1 = *(const float4*)(Bp + 64 * K);
        As[0][la_c + 0][la_r] = a0.x; As[0][la_c + 1][la_r] = a0.y;
        As[0][la_c + 2][la_r] = a0.z; As[0][la_c + 3][la_r] = a0.w;
        As[0][la_c + 0][la_r + 64] = a1.x; As[0][la_c + 1][la_r + 64] = a1.y;
        As[0][la_c + 2][la_r + 64] = a1.z; As[0][la_c + 3][la_r + 64] = a1.w;
        Bs[0][la_c + 0][la_r] = b0.x; Bs[0][la_c + 1][la_r] = b0.y;
        Bs[0][la_c + 2][la_r] = b0.z; Bs[0][la_c + 3][la_r] = b0.w;
        Bs[0][la_c + 0][la_r + 64] = b1.x; Bs[0][la_c + 1][la_r + 64] = b1.y;
        Bs[0][la_c + 2][la_r + 64] = b1.z; Bs[0][la_c + 3][la_r + 64] = b1.w;
    }
    __syncthreads();

    const int ntiles = K / BK;
    int buf = 0;
    for (int t = 0; t < ntiles; t++) {
        float4 pa0, pa1, pb0, pb1;
        const bool more = (t + 1 < ntiles);
        if (more) {
            const float* An = Ap + (t + 1) * BK;
            const float* Bn = Bp + (t + 1) * BK;
            pa0 = *(const float4*)(An);
            pa1 = *(const float4*)(An + 64 * K);
            pb0 = *(const float4*)(Bn);
            pb1 = *(const float4*)(Bn + 64 * K);
        }

        #pragma unroll
        for (int kk = 0; kk < BK; kk++) {
            float4 a0 = *(const float4*)&As[buf][kk][ty * 4];
            float4 a1 = *(const float4*)&As[buf][kk][ty * 4 + 64];
            float4 b0 = *(const float4*)&Bs[buf][kk][tx * 4];
            float4 b1 = *(const float4*)&Bs[buf][kk][tx * 4 + 64];
            float a[TM] = {a0.x, a0.y, a0.z, a0.w, a1.x, a1.y, a1.z, a1.w};
            float b[TN] = {b0.x, b0.y, b0.z, b0.w, b1.x, b1.y, b1.z, b1.w};
            #pragma unroll
            for (int i = 0; i < TM; i++)
                #pragma unroll
                for (int j = 0; j < TN; j++)
                    acc[i][j] += a[i] * b[j];
        }

        if (more) {
            const int nb = buf ^ 1;
            As[nb][la_c + 0][la_r] = pa0.x; As[nb][la_c + 1][la_r] = pa0.y;
            As[nb][la_c + 2][la_r] = pa0.z; As[nb][la_c + 3][la_r] = pa0.w;
            As[nb][la_c + 0][la_r + 64] = pa1.x; As[nb][la_c + 1][la_r + 64] = pa1.y;
            As[nb][la_c + 2][la_r + 64] = pa1.z; As[nb][la_c + 3][la_r + 64] = pa1.w;
            Bs[nb][la_c + 0][la_r] = pb0.x; Bs[nb][la_c + 1][la_r] = pb0.y;
            Bs[nb][la_c + 2][la_r] = pb0.z; Bs[nb][la_c + 3][la_r] = pb0.w;
            Bs[nb][la_c + 0][la_r + 64] = pb1.x; Bs[nb][la_c + 1][la_r + 64] = pb1.y;
            Bs[nb][la_c + 2][la_r + 64] = pb1.z; Bs[nb][la_c + 3][la_r + 64] = pb1.w;
            __syncthreads();
            buf = nb;
        }
    }

    float bv0[4], bv1[4];
    #pragma unroll
    for (int j = 0; j < 4; j++) {
        bv0[j] = bias[col0 + tx * 4 + j];
        bv1[j] = bias[col0 + 64 + tx * 4 + j];
    }

    #pragma unroll
    for (int i = 0; i < TM; i++) {
        const int r = row0 + ((i < 4) ? (ty * 4 + i) : (64 + ty * 4 + i - 4));
        float* Cr = C + (long)r * N + col0;
        *(float4*)(Cr + tx * 4) =
            make_float4(acc[i][0] + bv0[0], acc[i][1] + bv0[1],
                        acc[i][2] + bv0[2], acc[i][3] + bv0[3]);
        *(float4*)(Cr + 64 + tx * 4) =
            make_float4(acc[i][4] + bv1[0], acc[i][5] + bv1[1],
                        acc[i][6] + bv1[2], acc[i][7] + bv1[3]);
    }
}

// ---------------------------------------------------------------------------
// NT GEMM (no bias): C[m,n] = sum_k A[m,k] * B[n,k], batched via blockIdx.z
// ---------------------------------------------------------------------------
__global__ __launch_bounds__(256, 2) void gemm_nt(
    const float* __restrict__ A, const float* __restrict__ B,
    float* __restrict__ C,
    int M, int N, int K, long sA, long sB, long sC)
{
    A += (long)blockIdx.z * sA;
    B += (long)blockIdx.z * sB;
    C += (long)blockIdx.z * sC;

    __shared__ float As[2][BK][BM];
    __shared__ float Bs[2][BK][BN];

    const int tid = threadIdx.x;
    const int tx  = tid % 16;
    const int ty  = tid / 16;
    const int row0 = blockIdx.y * BM;
    const int col0 = blockIdx.x * BN;

    const int la_r = tid >> 2;
    const int la_c = (tid & 3) * 4;

    const float* Ap = A + (long)(row0 + la_r) * K + la_c;
    const float* Bp = B + (long)(col0 + la_r) * K + la_c;

    float acc[TM][TN];
    #pragma unroll
    for (int i = 0; i < TM; i++)
        #pragma unroll
        for (int j = 0; j < TN; j++) acc[i][j] = 0.f;

    {
        float4 a0 = *(const float4*)(Ap);
        float4 a1 = *(const float4*)(Ap + 64 * K);
        float4 b0 = *(const float4*)(Bp);
        float4 b1 = *(const float4*)(Bp + 64 * K);
        As[0][la_c + 0][la_r] = a0.x; As[0][la_c + 1][la_r] = a0.y;
        As[0][la_c + 2][la_r] = a0.z; As[0][la_c + 3][la_r] = a0.w;
        As[0][la_c + 0][la_r + 64] = a1.x; As[0][la_c + 1][la_r + 64] = a1.y;
        As[0][la_c + 2][la_r + 64] = a1.z; As[0][la_c + 3][la_r + 64] = a1.w;
        Bs[0][la_c + 0][la_r] = b0.x; Bs[0][la_c + 1][la_r] = b0.y;
        Bs[0][la_c + 2][la_r] = b0.z; Bs[0][la_c + 3][la_r] = b0.w;
        Bs[0][la_c + 0][la_r + 64] = b1.x; Bs[0][la_c + 1][la_r + 64] = b1.y;
        Bs[0][la_c + 2][la_r + 64] = b1.z; Bs[0][la_c + 3][la_r + 64] = b1.w;
    }
    __syncthreads();

    const int ntiles = K / BK;
    int buf = 0;
    for (int t = 0; t < ntiles; t++) {
        float4 pa0, pa1, pb0, pb1;
        const bool more = (t + 1 < ntiles);
        if (more) {
            const float* An = Ap + (t + 1) * BK;
            const float* Bn = Bp + (t + 1) * BK;
            pa0 = *(const float4*)(An);
            pa1 = *(const float4*)(An + 64 * K);
            pb0 = *(const float4*)(Bn);
            pb1 = *(const float4*)(Bn + 64 * K);
        }

        #pragma unroll
        for (int kk = 0; kk < BK; kk++) {
            float4 a0 = *(const float4*)&As[buf][kk][ty * 4];
            float4 a1 = *(const float4*)&As[buf][kk][ty * 4 + 64];
            float4 b0 = *(const float4*)&Bs[buf][kk][tx * 4];
            float4 b1 = *(const float4*)&Bs[buf][kk][tx * 4 + 64];
            float a[TM] = {a0.x, a0.y, a0.z, a0.w, a1.x, a1.y, a1.z, a1.w};
            float b[TN] = {b0.x, b0.y, b0.z, b0.w, b1.x, b1.y, b1.z, b1.w};
            #pragma unroll
            for (int i = 0; i < TM; i++)
                #pragma unroll
                for (int j = 0; j < TN; j++)
                    acc[i][j] += a[i] * b[j];
        }

        if (more) {
            const int nb = buf ^ 1;
            As[nb][la_c + 0][la_r] = pa0.x; As[nb][la_c + 1][la_r] = pa0.y;
            As[nb][la_c + 2][la_r] = pa0.z; As[nb][la_c + 3][la_r] = pa0.w;
            As[nb][la_c + 0][la_r + 64] = pa1.x; As[nb][la_c + 1][la_r + 64] = pa1.y;
            As[nb][la_c + 2][la_r + 64] = pa1.z; As[nb][la_c + 3][la_r + 64] = pa1.w;
            Bs[nb][la_c + 0][la_r] = pb0.x; Bs[nb][la_c + 1][la_r] = pb0.y;
            Bs[nb][la_c + 2][la_r] = pb0.z; Bs[nb][la_c + 3][la_r] = pb0.w;
            Bs[nb][la_c + 0][la_r + 64] = pb1.x; Bs[nb][la_c + 1][la_r + 64] = pb1.y;
            Bs[nb][la_c + 2][la_r + 64] = pb1.z; Bs[nb][la_c + 3][la_r + 64] = pb1.w;
            __syncthreads();
            buf = nb;
        }
    }

    #pragma unroll
    for (int i = 0; i < TM; i++) {
        const int r = row0 + ((i < 4) ? (ty * 4 + i) : (64 + ty * 4 + i - 4));
        float* Cr = C + (long)r * N + col0;
        *(float4*)(Cr + tx * 4) =
            make_float4(acc[i][0], acc[i][1], acc[i][2], acc[i][3]);
        *(float4*)(Cr + 64 + tx * 4) =
            make_float4(acc[i][4], acc[i][5], acc[i][6], acc[i][7]);
    }
}

// ---------------------------------------------------------------------------
// NN GEMM: C[m,n] = sum_k A[m,k] * B[k,n], batched via blockIdx.z
// ---------------------------------------------------------------------------
__global__ __launch_bounds__(256, 2) void gemm_nn(
    const float* __restrict__ A, const float* __restrict__ B,
    float* __restrict__ C,
    int M, int N, int K, long sA, long sB, long sC)
{
    A += (long)blockIdx.z * sA;
    B += (long)blockIdx.z * sB;
    C += (long)blockIdx.z * sC;

    __shared__ float As[2][BK][BM];
    __shared__ float Bs[2][BK][BN];

    const int tid = threadIdx.x;
    const int tx  = tid % 16;
    const int ty  = tid / 16;
    const int row0 = blockIdx.y * BM;
    const int col0 = blockIdx.x * BN;

    const int la_r = tid >> 2;
    const int la_c = (tid & 3) * 4;
    const int lb_r = tid >> 5;
    const int lb_c = (tid & 31) * 4;

    const float* Ap = A + (long)(row0 + la_r) * K + la_c;
    const float* Bp = B + (long)lb_r * N + col0 + lb_c;

    float acc[TM][TN];
    #pragma unroll
    for (int i = 0; i < TM; i++)
        #pragma unroll
        for (int j = 0; j < TN; j++) acc[i][j] = 0.f;

    {
        float4 a0 = *(const float4*)(Ap);
        float4 a1 = *(const float4*)(Ap + 64 * K);
        float4 b0 = *(const float4*)(Bp);
        float4 b1 = *(const float4*)(Bp + 8 * N);
        As[0][la_c + 0][la_r] = a0.x; As[0][la_c + 1][la_r] = a0.y;
        As[0][la_c + 2][la_r] = a0.z; As[0][la_c + 3][la_r] = a0.w;
        As[0][la_c + 0][la_r + 64] = a1.x; As[0][la_c + 1][la_r + 64] = a1.y;
        As[0][la_c + 2][la_r + 64] = a1.z; As[0][la_c + 3][la_r + 64] = a1.w;
        *(float4*)&Bs[0][lb_r][lb_c]     = b0;
        *(float4*)&Bs[0][lb_r + 8][lb_c] = b1;
    }
    __syncthreads();

    const int ntiles = K / BK;
    int buf = 0;
    for (int t = 0; t < ntiles; t++) {
        float4 pa0, pa1, pb0, pb1;
        const bool more = (t + 1 < ntiles);
        if (more) {
            const float* An = Ap + (t + 1) * BK;
            const float* Bn = Bp + (long)(t + 1) * BK * N;
            pa0 = *(const float4*)(An);
            pa1 = *(const float4*)(An + 64 * K);
            pb0 = *(const float4*)(Bn);
            pb1 = *(const float4*)(Bn + 8 * N);
        }

        #pragma unroll
        for (int kk = 0; kk < BK; kk++) {
            float4 a0 = *(const float4*)&As[buf][kk][ty * 4];
            float4 a1 = *(const float4*)&As[buf][kk][ty * 4 + 64];
            float4 b0 = *(const float4*)&Bs[buf][kk][tx * 4];
            float4 b1 = *(const float4*)&Bs[buf][kk][tx * 4 + 64];
            float a[TM] = {a0.x, a0.y, a0.z, a0.w, a1.x, a1.y, a1.z, a1.w};
            float b[TN] = {b0.x, b0.y, b0.z, b0.w, b1.x, b1.y, b1.z, b1.w};
            #pragma unroll
            for (int i = 0; i < TM; i++)
                #pragma unroll
                for (int j = 0; j < TN; j++)
                    acc[i][j] += a[i] * b[j];
        }

        if (more) {
            const int nb = buf ^ 1;
            As[nb][la_c + 0][la_r] = pa0.x; As[nb][la_c + 1][la_r] = pa0.y;
            As[nb][la_c + 2][la_r] = pa0.z; As[nb][la_c + 3][la_r] = pa0.w;
            As[nb][la_c + 0][la_r + 64] = pa1.x; As[nb][la_c + 1][la_r + 64] = pa1.y;
            As[nb][la_c + 2][la_r + 64] = pa1.z; As[nb][la_c + 3][la_r + 64] = pa1.w;
            *(float4*)&Bs[nb][lb_r][lb_c]     = pb0;
            *(float4*)&Bs[nb][lb_r + 8][lb_c] = pb1;
            __syncthreads();
            buf = nb;
        }
    }

    #pragma unroll
    for (int i = 0; i < TM; i++) {
        const int r = row0 + ((i < 4) ? (ty * 4 + i) : (64 + ty * 4 + i - 4));
        float* Cr = C + (long)r * N + col0;
        *(float4*)(Cr + tx * 4) =
            make_float4(acc[i][0], acc[i][1], acc[i][2], acc[i][3]);
        *(float4*)(Cr + 64 + tx * 4) =
            make_float4(acc[i][4], acc[i][5], acc[i][6], acc[i][7]);
    }
}

// ---------------------------------------------------------------------------
// Row softmax over P rows of length SEQ (in place). One block per row.
// Final cross-warp reductions done in lane space (no serial warp-0 loop).
// ---------------------------------------------------------------------------
__global__ __launch_bounds__(256) void softmax_rows(float* __restrict__ P)
{
    float* p = P + (long)blockIdx.x * SEQ;
    const int tid  = threadIdx.x;
    const int lane = tid & 31;
    const int warp = tid >> 5;

    __shared__ float redm[8];
    __shared__ float reds[8];

    float4 v0 = ((const float4*)p)[tid * 2];
    float4 v1 = ((const float4*)p)[tid * 2 + 1];
    float x[8] = {v0.x, v0.y, v0.z, v0.w, v1.x, v1.y, v1.z, v1.w};

    // row max
    float m = x[0];
    #pragma unroll
    for (int i = 1; i < 8; i++) m = fmaxf(m, x[i]);
    #pragma unroll
    for (int off = 16; off > 0; off >>= 1)
        m = fmaxf(m, __shfl_xor_sync(0xffffffffu, m, off));
    if (lane == 0) redm[warp] = m;
    __syncthreads();
    {
        float t = redm[lane & 7];
        #pragma unroll
        for (int off = 4; off > 0; off >>= 1)
            t = fmaxf(t, __shfl_xor_sync(0xffffffffu, t, off));
        m = t;  // all lanes now hold the block max
    }

    // exp + row sum
    float s = 0.f;
    #pragma unroll
    for (int i = 0; i < 8; i++) { x[i] = __expf(x[i] - m); s += x[i]; }
    #pragma unroll
    for (int off = 16; off > 0; off >>= 1)
        s += __shfl_xor_sync(0xffffffffu, s, off);
    if (lane == 0) reds[warp] = s;
    __syncthreads();
    float inv;
    {
        float t = reds[lane & 7];
        #pragma unroll
        for (int off = 4; off > 0; off >>= 1)
            t += __shfl_xor_sync(0xffffffffu, t, off);
        inv = 1.0f / t;
    }

    ((float4*)p)[tid * 2]     = make_float4(x[0] * inv, x[1] * inv, x[2] * inv, x[3] * inv);
    ((float4*)p)[tid * 2 + 1] = make_float4(x[4] * inv, x[5] * inv, x[6] * inv, x[7] * inv);
}

// ---------------------------------------------------------------------------
// attention_scores[b,k] = sum_q P[b,q,k]  (coalesced column reduction, MLP=8)
// ---------------------------------------------------------------------------
__global__ __launch_bounds__(256) void colsum(
    const float* __restrict__ P, float* __restrict__ scores)
{
    const int k = blockIdx.x * blockDim.x + threadIdx.x;
    const float* Pb = P + (long)blockIdx.y * SEQ * SEQ;
    float s0 = 0.f, s1 = 0.f, s2 = 0.f, s3 = 0.f;
    float s4 = 0.f, s5 = 0.f, s6 = 0.f, s7 = 0.f;
    for (int q = 0; q < SEQ; q += 8) {
        s0 += Pb[(long)(q + 0) * SEQ + k];
        s1 += Pb[(long)(q + 1) * SEQ + k];
        s2 += Pb[(long)(q + 2) * SEQ + k];
        s3 += Pb[(long)(q + 3) * SEQ + k];
        s4 += Pb[(long)(q + 4) * SEQ + k];
        s5 += Pb[(long)(q + 5) * SEQ + k];
        s6 += Pb[(long)(q + 6) * SEQ + k];
        s7 += Pb[(long)(q + 7) * SEQ + k];
    }
    scores[(long)blockIdx.y * SEQ + k] =
        ((s0 + s1) + (s2 + s3)) + ((s4 + s5) + (s6 + s7));
}

// ---------------------------------------------------------------------------
// Launch
// ---------------------------------------------------------------------------
extern "C" void kernel_launch(void* const* d_in, const int* in_sizes, int n_in,
                              void* d_out, int out_size)
{
    const float* X  = (const float*)d_in[0];
    const float* Wq = (const float*)d_in[1];
    const float* bq = (const float*)d_in[2];
    const float* Wk = (const float*)d_in[3];
    const float* bk = (const float*)d_in[4];
    const float* Wv = (const float*)d_in[5];
    const float* bv = (const float*)d_in[6];
    float* out = (float*)d_out;

    float *Q, *K, *V, *P;
    cudaGetSymbolAddress((void**)&Q, g_Q);
    cudaGetSymbolAddress((void**)&K, g_K);
    cudaGetSymbolAddress((void**)&V, g_V);
    cudaGetSymbolAddress((void**)&P, g_P);

    dim3 blk(256);

    // 1) QKV projections fused into one launch (grid.z = 3)
    dim3 gproj(HID / BN, MTOT / BM, 3);
    gemm_qkv<<<gproj, blk>>>(X, Wq, bq, Wk, bk, Wv, bv, Q, K, V);

    // 2) logits: P[b] = Q[b] @ K[b]^T   [2048,2048]
    dim3 gsc(SEQ / BN, SEQ / BM, BATCH);
    gemm_nt<<<gsc, blk>>>(Q, K, P, SEQ, SEQ, HID,
                          (long)SEQ * HID, (long)SEQ * HID, (long)SEQ * SEQ);

    // 3) row softmax in place
    softmax_rows<<<BATCH * SEQ, 256>>>(P);

    // 4) attention_scores = column sums of probs
    colsum<<<dim3(SEQ / 256, BATCH), 256>>>(P, out + (long)MTOT * HID);

    // 5) context: out[b] = P[b] @ V[b]   [2048,1024]
    dim3 gctx(HID / BN, SEQ / BM, BATCH);
    gemm_nn<<<gctx, blk>>>(P, V, out, SEQ, HID, SEQ,
                           (long)SEQ * SEQ, (long)SEQ * HID, (long)SEQ * HID);
}

// round 15
// speedup vs baseline: 1.4712x; 1.4712x over previous
#include <cuda_runtime.h>
#include <cuda_bf16.h>
#include <mma.h>

using namespace nvcuda;

#define BATCH 4
#define SEQ   2048
#define HID   1024
#define MTOT  8192
#define BM 128
#define BN 128
#define BK 16
#define LDA 24
#define LDBNN 136
#define LDST 20

// ---------------- scratch (device globals) ----------------
__device__ __nv_bfloat16 g_Xh[(size_t)MTOT * HID];
__device__ __nv_bfloat16 g_Xl[(size_t)MTOT * HID];
__device__ __nv_bfloat16 g_Wh[(size_t)3 * HID * HID];
__device__ __nv_bfloat16 g_Wl[(size_t)3 * HID * HID];
__device__ __nv_bfloat16 g_QKVh[(size_t)3 * MTOT * HID];
__device__ __nv_bfloat16 g_QKVl[(size_t)3 * MTOT * HID];
__device__ float g_P[(size_t)BATCH * SEQ * SEQ];
__device__ __nv_bfloat16 g_Ph[(size_t)BATCH * SEQ * SEQ];
__device__ __nv_bfloat16 g_Pl[(size_t)BATCH * SEQ * SEQ];
__device__ float g_part[(size_t)8 * BATCH * SEQ];

// ---------------------------------------------------------------------------
// QKV: NT GEMM, split-bf16 in, bias add, split-bf16 out. grid.z = 0,1,2.
// C[m,n] = sum_k X[m,k] * W[n,k] + bias[n]
// ---------------------------------------------------------------------------
__global__ __launch_bounds__(256, 2) void gemm_qkv_w(
    const __nv_bfloat16* __restrict__ Xh, const __nv_bfloat16* __restrict__ Xl,
    const __nv_bfloat16* __restrict__ Wh, const __nv_bfloat16* __restrict__ Wl,
    const float* __restrict__ bq, const float* __restrict__ bk, const float* __restrict__ bv,
    __nv_bfloat16* __restrict__ Qh, __nv_bfloat16* __restrict__ Ql)
{
    __shared__ __align__(16) __nv_bfloat16 sAh[BM][LDA];
    __shared__ __align__(16) __nv_bfloat16 sAl[BM][LDA];
    __shared__ __align__(16) __nv_bfloat16 sBh[BM][LDA];
    __shared__ __align__(16) __nv_bfloat16 sBl[BM][LDA];
    __shared__ __align__(16) float stg[8][16 * LDST];

    const int z = blockIdx.z;
    const __nv_bfloat16* Bh = Wh + (size_t)z * HID * HID;
    const __nv_bfloat16* Bl = Wl + (size_t)z * HID * HID;
    const float* bias = (z == 0) ? bq : ((z == 1) ? bk : bv);
    __nv_bfloat16* Ch = Qh + (size_t)z * MTOT * HID;
    __nv_bfloat16* Cl = Ql + (size_t)z * MTOT * HID;

    const int tid = threadIdx.x;
    const int lane = tid & 31;
    const int wid = tid >> 5;
    const int wr = wid >> 2;
    const int wc = wid & 3;
    const int row0 = blockIdx.y * BM;
    const int col0 = blockIdx.x * BN;

    const int arow = tid >> 1;
    const int ak8 = (tid & 1) * 8;

    wmma::fragment<wmma::accumulator, 16, 16, 16, float> acc[4][2];
    for (int m = 0; m < 4; m++)
        for (int n = 0; n < 2; n++)
            wmma::fill_fragment(acc[m][n], 0.0f);

    for (int k0 = 0; k0 < HID; k0 += BK) {
        *(uint4*)(&sAh[arow][ak8]) = *(const uint4*)(Xh + (size_t)(row0 + arow) * HID + k0 + ak8);
        *(uint4*)(&sAl[arow][ak8]) = *(const uint4*)(Xl + (size_t)(row0 + arow) * HID + k0 + ak8);
        *(uint4*)(&sBh[arow][ak8]) = *(const uint4*)(Bh + (size_t)(col0 + arow) * HID + k0 + ak8);
        *(uint4*)(&sBl[arow][ak8]) = *(const uint4*)(Bl + (size_t)(col0 + arow) * HID + k0 + ak8);
        __syncthreads();

        wmma::fragment<wmma::matrix_a, 16, 16, 16, __nv_bfloat16, wmma::row_major> fa[4];
        wmma::fragment<wmma::matrix_b, 16, 16, 16, __nv_bfloat16, wmma::col_major> fbh[2];
        wmma::fragment<wmma::matrix_b, 16, 16, 16, __nv_bfloat16, wmma::col_major> fbl;

        for (int m = 0; m < 4; m++)
            wmma::load_matrix_sync(fa[m], &sAh[wr * 64 + m * 16][0], LDA);
        for (int n = 0; n < 2; n++)
            wmma::load_matrix_sync(fbh[n], &sBh[wc * 32 + n * 16][0], LDA);
        for (int m = 0; m < 4; m++)
            for (int n = 0; n < 2; n++)
                wmma::mma_sync(acc[m][n], fa[m], fbh[n], acc[m][n]);
        for (int n = 0; n < 2; n++) {
            wmma::load_matrix_sync(fbl, &sBl[wc * 32 + n * 16][0], LDA);
            for (int m = 0; m < 4; m++)
                wmma::mma_sync(acc[m][n], fa[m], fbl, acc[m][n]);
        }
        for (int m = 0; m < 4; m++)
            wmma::load_matrix_sync(fa[m], &sAl[wr * 64 + m * 16][0], LDA);
        for (int m = 0; m < 4; m++)
            for (int n = 0; n < 2; n++)
                wmma::mma_sync(acc[m][n], fa[m], fbh[n], acc[m][n]);
        __syncthreads();
    }

    const int erow = lane >> 1;
    const int ecol = (lane & 1) * 8;
    for (int m = 0; m < 4; m++) {
        for (int n = 0; n < 2; n++) {
            wmma::store_matrix_sync(&stg[wid][0], acc[m][n], LDST, wmma::mem_row_major);
            __syncwarp();
            const int r = row0 + wr * 64 + m * 16 + erow;
            const int c = col0 + wc * 32 + n * 16 + ecol;
            size_t o = (size_t)r * HID + c;
            for (int j = 0; j < 8; j++) {
                float v = stg[wid][erow * LDST + ecol + j] + bias[c + j];
                __nv_bfloat16 hh = __float2bfloat16(v);
                Ch[o + j] = hh;
                Cl[o + j] = __float2bfloat16(v - __bfloat162float(hh));
            }
            __syncwarp();
        }
    }
}

// ---------------------------------------------------------------------------
// Logits: NT GEMM, split-bf16 in, fp32 out. grid.z = batch.
// C[m,n] = sum_k Q[m,k] * K[n,k]
// ---------------------------------------------------------------------------
__global__ __launch_bounds__(256, 2) void gemm_nt_w(
    const __nv_bfloat16* __restrict__ Ah0, const __nv_bfloat16* __restrict__ Al0,
    const __nv_bfloat16* __restrict__ Bh0, const __nv_bfloat16* __restrict__ Bl0,
    float* __restrict__ Cf)
{
    __shared__ __align__(16) __nv_bfloat16 sAh[BM][LDA];
    __shared__ __align__(16) __nv_bfloat16 sAl[BM][LDA];
    __shared__ __align__(16) __nv_bfloat16 sBh[BM][LDA];
    __shared__ __align__(16) __nv_bfloat16 sBl[BM][LDA];

    const int z = blockIdx.z;
    const __nv_bfloat16* Ah = Ah0 + (size_t)z * SEQ * HID;
    const __nv_bfloat16* Al = Al0 + (size_t)z * SEQ * HID;
    const __nv_bfloat16* Bh = Bh0 + (size_t)z * SEQ * HID;
    const __nv_bfloat16* Bl = Bl0 + (size_t)z * SEQ * HID;
    float* C = Cf + (size_t)z * SEQ * SEQ;

    const int tid = threadIdx.x;
    const int wid = tid >> 5;
    const int wr = wid >> 2;
    const int wc = wid & 3;
    const int row0 = blockIdx.y * BM;
    const int col0 = blockIdx.x * BN;

    const int arow = tid >> 1;
    const int ak8 = (tid & 1) * 8;

    wmma::fragment<wmma::accumulator, 16, 16, 16, float> acc[4][2];
    for (int m = 0; m < 4; m++)
        for (int n = 0; n < 2; n++)
            wmma::fill_fragment(acc[m][n], 0.0f);

    for (int k0 = 0; k0 < HID; k0 += BK) {
        *(uint4*)(&sAh[arow][ak8]) = *(const uint4*)(Ah + (size_t)(row0 + arow) * HID + k0 + ak8);
        *(uint4*)(&sAl[arow][ak8]) = *(const uint4*)(Al + (size_t)(row0 + arow) * HID + k0 + ak8);
        *(uint4*)(&sBh[arow][ak8]) = *(const uint4*)(Bh + (size_t)(col0 + arow) * HID + k0 + ak8);
        *(uint4*)(&sBl[arow][ak8]) = *(const uint4*)(Bl + (size_t)(col0 + arow) * HID + k0 + ak8);
        __syncthreads();

        wmma::fragment<wmma::matrix_a, 16, 16, 16, __nv_bfloat16, wmma::row_major> fa[4];
        wmma::fragment<wmma::matrix_b, 16, 16, 16, __nv_bfloat16, wmma::col_major> fbh[2];
        wmma::fragment<wmma::matrix_b, 16, 16, 16, __nv_bfloat16, wmma::col_major> fbl;

        for (int m = 0; m < 4; m++)
            wmma::load_matrix_sync(fa[m], &sAh[wr * 64 + m * 16][0], LDA);
        for (int n = 0; n < 2; n++)
            wmma::load_matrix_sync(fbh[n], &sBh[wc * 32 + n * 16][0], LDA);
        for (int m = 0; m < 4; m++)
            for (int n = 0; n < 2; n++)
                wmma::mma_sync(acc[m][n], fa[m], fbh[n], acc[m][n]);
        for (int n = 0; n < 2; n++) {
            wmma::load_matrix_sync(fbl, &sBl[wc * 32 + n * 16][0], LDA);
            for (int m = 0; m < 4; m++)
                wmma::mma_sync(acc[m][n], fa[m], fbl, acc[m][n]);
        }
        for (int m = 0; m < 4; m++)
            wmma::load_matrix_sync(fa[m], &sAl[wr * 64 + m * 16][0], LDA);
        for (int m = 0; m < 4; m++)
            for (int n = 0; n < 2; n++)
                wmma::mma_sync(acc[m][n], fa[m], fbh[n], acc[m][n]);
        __syncthreads();
    }

    for (int m = 0; m < 4; m++)
        for (int n = 0; n < 2; n++)
            wmma::store_matrix_sync(
                C + (size_t)(row0 + wr * 64 + m * 16) * SEQ + col0 + wc * 32 + n * 16,
                acc[m][n], SEQ, wmma::mem_row_major);
}

// ---------------------------------------------------------------------------
// Context: NN GEMM, split-bf16 in, fp32 out. grid.z = batch.
// C[m,n] = sum_k P[m,k] * V[k,n]
// ---------------------------------------------------------------------------
__global__ __launch_bounds__(256, 2) void gemm_nn_w(
    const __nv_bfloat16* __restrict__ Ah0, const __nv_bfloat16* __restrict__ Al0,
    const __nv_bfloat16* __restrict__ Bh0, const __nv_bfloat16* __restrict__ Bl0,
    float* __restrict__ Cf)
{
    __shared__ __align__(16) __nv_bfloat16 sAh[BM][LDA];
    __shared__ __align__(16) __nv_bfloat16 sAl[BM][LDA];
    __shared__ __align__(16) __nv_bfloat16 sBh[BK][LDBNN];
    __shared__ __align__(16) __nv_bfloat16 sBl[BK][LDBNN];

    const int z = blockIdx.z;
    const __nv_bfloat16* Ah = Ah0 + (size_t)z * SEQ * SEQ;
    const __nv_bfloat16* Al = Al0 + (size_t)z * SEQ * SEQ;
    const __nv_bfloat16* Bh = Bh0 + (size_t)z * SEQ * HID;
    const __nv_bfloat16* Bl = Bl0 + (size_t)z * SEQ * HID;
    float* C = Cf + (size_t)z * SEQ * HID;

    const int tid = threadIdx.x;
    const int wid = tid >> 5;
    const int wr = wid >> 2;
    const int wc = wid & 3;
    const int row0 = blockIdx.y * BM;
    const int col0 = blockIdx.x * BN;

    const int arow = tid >> 1;
    const int ak8 = (tid & 1) * 8;
    const int brow = tid >> 4;
    const int bn8 = (tid & 15) * 8;

    wmma::fragment<wmma::accumulator, 16, 16, 16, float> acc[4][2];
    for (int m = 0; m < 4; m++)
        for (int n = 0; n < 2; n++)
            wmma::fill_fragment(acc[m][n], 0.0f);

    for (int k0 = 0; k0 < SEQ; k0 += BK) {
        *(uint4*)(&sAh[arow][ak8]) = *(const uint4*)(Ah + (size_t)(row0 + arow) * SEQ + k0 + ak8);
        *(uint4*)(&sAl[arow][ak8]) = *(const uint4*)(Al + (size_t)(row0 + arow) * SEQ + k0 + ak8);
        *(uint4*)(&sBh[brow][bn8]) = *(const uint4*)(Bh + (size_t)(k0 + brow) * HID + col0 + bn8);
        *(uint4*)(&sBl[brow][bn8]) = *(const uint4*)(Bl + (size_t)(k0 + brow) * HID + col0 + bn8);
        __syncthreads();

        wmma::fragment<wmma::matrix_a, 16, 16, 16, __nv_bfloat16, wmma::row_major> fa[4];
        wmma::fragment<wmma::matrix_b, 16, 16, 16, __nv_bfloat16, wmma::row_major> fbh[2];
        wmma::fragment<wmma::matrix_b, 16, 16, 16, __nv_bfloat16, wmma::row_major> fbl;

        for (int m = 0; m < 4; m++)
            wmma::load_matrix_sync(fa[m], &sAh[wr * 64 + m * 16][0], LDA);
        for (int n = 0; n < 2; n++)
            wmma::load_matrix_sync(fbh[n], &sBh[0][wc * 32 + n * 16], LDBNN);
        for (int m = 0; m < 4; m++)
            for (int n = 0; n < 2; n++)
                wmma::mma_sync(acc[m][n], fa[m], fbh[n], acc[m][n]);
        for (int n = 0; n < 2; n++) {
            wmma::load_matrix_sync(fbl, &sBl[0][wc * 32 + n * 16], LDBNN);
            for (int m = 0; m < 4; m++)
                wmma::mma_sync(acc[m][n], fa[m], fbl, acc[m][n]);
        }
        for (int m = 0; m < 4; m++)
            wmma::load_matrix_sync(fa[m], &sAl[wr * 64 + m * 16][0], LDA);
        for (int m = 0; m < 4; m++)
            for (int n = 0; n < 2; n++)
                wmma::mma_sync(acc[m][n], fa[m], fbh[n], acc[m][n]);
        __syncthreads();
    }

    for (int m = 0; m < 4; m++)
        for (int n = 0; n < 2; n++)
            wmma::store_matrix_sync(
                C + (size_t)(row0 + wr * 64 + m * 16) * HID + col0 + wc * 32 + n * 16,
                acc[m][n], HID, wmma::mem_row_major);
}

// ---------------------------------------------------------------------------
// fp32 -> split bf16 pair, 4 elems/thread
// ---------------------------------------------------------------------------
__global__ __launch_bounds__(256) void conv_split(
    const float* __restrict__ s, __nv_bfloat16* __restrict__ h, __nv_bfloat16* __restrict__ l)
{
    size_t i = (size_t)blockIdx.x * 256 + threadIdx.x;
    float4 v = ((const float4*)s)[i];
    size_t o = i * 4;
    __nv_bfloat16 h0 = __float2bfloat16(v.x);
    __nv_bfloat16 h1 = __float2bfloat16(v.y);
    __nv_bfloat16 h2 = __float2bfloat16(v.z);
    __nv_bfloat16 h3 = __float2bfloat16(v.w);
    h[o + 0] = h0;
    h[o + 1] = h1;
    h[o + 2] = h2;
    h[o + 3] = h3;
    l[o + 0] = __float2bfloat16(v.x - __bfloat162float(h0));
    l[o + 1] = __float2bfloat16(v.y - __bfloat162float(h1));
    l[o + 2] = __float2bfloat16(v.z - __bfloat162float(h2));
    l[o + 3] = __float2bfloat16(v.w - __bfloat162float(h3));
}

// ---------------------------------------------------------------------------
// Row softmax: fp32 logits in, split-bf16 probs out. One block per row.
// ---------------------------------------------------------------------------
__global__ __launch_bounds__(256) void softmax_rows(
    const float* __restrict__ P, __nv_bfloat16* __restrict__ Ph, __nv_bfloat16* __restrict__ Pl)
{
    const float* p = P + (size_t)blockIdx.x * SEQ;
    const int tid = threadIdx.x;
    const int lane = tid & 31;
    const int warp = tid >> 5;
    __shared__ float redm[8];
    __shared__ float reds[8];

    float4 v0 = ((const float4*)p)[tid * 2];
    float4 v1 = ((const float4*)p)[tid * 2 + 1];
    float x[8] = {v0.x, v0.y, v0.z, v0.w, v1.x, v1.y, v1.z, v1.w};

    float m = x[0];
    for (int i = 1; i < 8; i++) m = fmaxf(m, x[i]);
    for (int off = 16; off > 0; off >>= 1)
        m = fmaxf(m, __shfl_xor_sync(0xffffffffu, m, off));
    if (lane == 0) redm[warp] = m;
    __syncthreads();
    {
        float t = redm[lane & 7];
        for (int off = 4; off > 0; off >>= 1)
            t = fmaxf(t, __shfl_xor_sync(0xffffffffu, t, off));
        m = t;
    }

    float s = 0.f;
    for (int i = 0; i < 8; i++) {
        x[i] = __expf(x[i] - m);
        s += x[i];
    }
    for (int off = 16; off > 0; off >>= 1)
        s += __shfl_xor_sync(0xffffffffu, s, off);
    if (lane == 0) reds[warp] = s;
    __syncthreads();
    float inv;
    {
        float t = reds[lane & 7];
        for (int off = 4; off > 0; off >>= 1)
            t += __shfl_xor_sync(0xffffffffu, t, off);
        inv = 1.0f / t;
    }

    size_t base = (size_t)blockIdx.x * SEQ + (size_t)tid * 8;
    for (int i = 0; i < 8; i++) {
        float pv = x[i] * inv;
        __nv_bfloat16 hh = __float2bfloat16(pv);
        Ph[base + i] = hh;
        Pl[base + i] = __float2bfloat16(pv - __bfloat162float(hh));
    }
}

// ---------------------------------------------------------------------------
// attention_scores: split-K column sums of (Ph + Pl)
// ---------------------------------------------------------------------------
__global__ __launch_bounds__(256) void colsum_part(
    const __nv_bfloat16* __restrict__ Ph, const __nv_bfloat16* __restrict__ Pl,
    float* __restrict__ part)
{
    const int k = blockIdx.x * 256 + threadIdx.x;
    const int b = blockIdx.y;
    const int qz = blockIdx.z;
    const __nv_bfloat16* ph = Ph + ((size_t)b * SEQ + (size_t)qz * 256) * SEQ + k;
    const __nv_bfloat16* pl = Pl + ((size_t)b * SEQ + (size_t)qz * 256) * SEQ + k;
    float s = 0.f;
    for (int q = 0; q < 256; q++)
        s += __bfloat162float(ph[(size_t)q * SEQ]) + __bfloat162float(pl[(size_t)q * SEQ]);
    part[((size_t)qz * BATCH + b) * SEQ + k] = s;
}

__global__ __launch_bounds__(256) void colsum_fin(
    const float* __restrict__ part, float* __restrict__ scores)
{
    const int i = blockIdx.x * 256 + threadIdx.x;
    float s = 0.f;
    for (int zz = 0; zz < 8; zz++) s += part[(size_t)zz * BATCH * SEQ + i];
    scores[i] = s;
}

// ---------------------------------------------------------------------------
// Launch
// ---------------------------------------------------------------------------
extern "C" void kernel_launch(void* const* d_in, const int* in_sizes, int n_in,
                              void* d_out, int out_size)
{
    const float* X  = (const float*)d_in[0];
    const float* Wq = (const float*)d_in[1];
    const float* bq = (const float*)d_in[2];
    const float* Wk = (const float*)d_in[3];
    const float* bk = (const float*)d_in[4];
    const float* Wv = (const float*)d_in[5];
    const float* bv = (const float*)d_in[6];
    float* out = (float*)d_out;

    __nv_bfloat16 *Xh, *Xl, *Wh, *Wl, *QKVh, *QKVl, *Ph, *Pl;
    float *P, *part;
    cudaGetSymbolAddress((void**)&Xh, g_Xh);
    cudaGetSymbolAddress((void**)&Xl, g_Xl);
    cudaGetSymbolAddress((void**)&Wh, g_Wh);
    cudaGetSymbolAddress((void**)&Wl, g_Wl);
    cudaGetSymbolAddress((void**)&QKVh, g_QKVh);
    cudaGetSymbolAddress((void**)&QKVl, g_QKVl);
    cudaGetSymbolAddress((void**)&P,  g_P);
    cudaGetSymbolAddress((void**)&Ph, g_Ph);
    cudaGetSymbolAddress((void**)&Pl, g_Pl);
    cudaGetSymbolAddress((void**)&part, g_part);

    const long WSZ = (long)HID * HID;
    const long QSZ = (long)MTOT * HID;

    // 0) fp32 -> split bf16
    conv_split<<<(int)((long)MTOT * HID / 4 / 256), 256>>>(X, Xh, Xl);
    conv_split<<<(int)(WSZ / 4 / 256), 256>>>(Wq, Wh, Wl);
    conv_split<<<(int)(WSZ / 4 / 256), 256>>>(Wk, Wh + WSZ, Wl + WSZ);
    conv_split<<<(int)(WSZ / 4 / 256), 256>>>(Wv, Wh + 2 * WSZ, Wl + 2 * WSZ);

    // 1) QKV projections (NT + bias), split-bf16 out
    gemm_qkv_w<<<dim3(HID / BN, MTOT / BM, 3), 256>>>(
        Xh, Xl, Wh, Wl, bq, bk, bv, QKVh, QKVl);

    // 2) logits: P[b] = Q[b] @ K[b]^T, fp32 out
    gemm_nt_w<<<dim3(SEQ / BN, SEQ / BM, BATCH), 256>>>(
        QKVh, QKVl, QKVh + QSZ, QKVl + QSZ, P);

    // 3) softmax -> split-bf16 probs
    softmax_rows<<<BATCH * SEQ, 256>>>(P, Ph, Pl);

    // 4) scores = column sums
    colsum_part<<<dim3(SEQ / 256, BATCH, 8), 256>>>(Ph, Pl, part);
    colsum_fin<<<BATCH * SEQ / 256, 256>>>(part, out + QSZ);

    // 5) context: out[b] = P[b] @ V[b], fp32 out
    gemm_nn_w<<<dim3(HID / BN, SEQ / BM, BATCH), 256>>>(
        Ph, Pl, QKVh + 2 * QSZ, QKVl + 2 * QSZ, out);
}